// round 16
// baseline (speedup 1.0000x reference)
#include <cuda_runtime.h>
#include <cuda_fp16.h>
#include <cstdint>

#define BATCH 8
#define SEQ   2048
#define EMB   1024
#define HEAD  64
#define NTOK  (BATCH*SEQ)   // 16384
#define LOG2E 1.4426950408889634f
#define QSCALE (0.03125f * LOG2E)   // C^-0.5 * log2(e)

// ---------------------------------------------------------------------------
// PTX helpers (family-portable only)
// ---------------------------------------------------------------------------
__device__ __forceinline__ uint32_t packh2(float lo, float hi) {
    __half2 h = __floats2half2_rn(lo, hi);
    return *reinterpret_cast<uint32_t*>(&h);
}
__device__ __forceinline__ void mma_f16(float* d, const uint32_t* a, const uint32_t* b) {
    asm volatile(
        "mma.sync.aligned.m16n8k16.row.col.f32.f16.f16.f32 "
        "{%0,%1,%2,%3}, {%4,%5,%6,%7}, {%8,%9}, {%0,%1,%2,%3};"
        : "+f"(d[0]), "+f"(d[1]), "+f"(d[2]), "+f"(d[3])
        : "r"(a[0]), "r"(a[1]), "r"(a[2]), "r"(a[3]), "r"(b[0]), "r"(b[1]));
}
__device__ __forceinline__ uint32_t s32(const void* p) {
    return (uint32_t)__cvta_generic_to_shared(p);
}
#define CP_ASYNC16(dst, src) \
    asm volatile("cp.async.cg.shared.global [%0], [%1], 16;" :: "r"(dst), "l"(src))
#define CP_COMMIT() asm volatile("cp.async.commit_group;" ::: "memory")
#define CP_WAIT0()  asm volatile("cp.async.wait_group 0;" ::: "memory")

// ---------------------------------------------------------------------------
// device scratch
// ---------------------------------------------------------------------------
__device__ __half g_Qh[NTOK*HEAD];
__device__ __half g_Kh[NTOK*HEAD];
__device__ __half g_Vth[HEAD*NTOK];
__device__ __half g_Wth[3*HEAD*EMB];

// ---------------------------------------------------------------------------
// Kernel 0: transpose W [1024][64] fp32 -> g_Wth [64][1024] fp16.
// grid (64, 3), 16 k-rows per tile, 256 threads (1 ld + 1 st per thread).
// ---------------------------------------------------------------------------
__global__ void wth_kernel(const float* __restrict__ Wq,
                           const float* __restrict__ Wk,
                           const float* __restrict__ Wv)
{
    __shared__ float t[16][65];
    const float* W = (blockIdx.y == 0) ? Wq : (blockIdx.y == 1) ? Wk : Wv;
    __half* Out = g_Wth + (size_t)blockIdx.y * HEAD * EMB;
    const int k0 = blockIdx.x * 16;
    const int tid = threadIdx.x;

    {
        int c = tid & 15, r = tid >> 4;               // r = k row (16)
        float4 v = *(const float4*)&W[(size_t)(k0 + r) * HEAD + 4*c];
        t[r][4*c + 0] = v.x; t[r][4*c + 1] = v.y;
        t[r][4*c + 2] = v.z; t[r][4*c + 3] = v.w;
    }
    __syncthreads();
    {
        int c = tid & 3, r = tid >> 2;                // r = n row (64)
        uint2 u;
        u.x = packh2(t[4*c + 0][r], t[4*c + 1][r]);
        u.y = packh2(t[4*c + 2][r], t[4*c + 3][r]);
        *(uint2*)&Out[(size_t)r * EMB + k0 + 4*c] = u;
    }
}

// ---------------------------------------------------------------------------
// Kernel 1: QKV projection, mma.sync fp16 (unchanged from R15 — passed).
// ---------------------------------------------------------------------------
__global__ __launch_bounds__(256, 1) void qkv_mma(
    const float* __restrict__ X)
{
    __shared__ __half Xs[128*72];
    __shared__ __half Wt[3*64*72];

    const int tid  = threadIdx.x;
    const int wid  = tid >> 5;
    const int lane = tid & 31;
    const int mw   = wid >> 1;
    const int nw   = wid & 1;
    const int m0   = blockIdx.x * 128;
    const int r = lane >> 2;
    const int c = lane & 3;

    const uint32_t* Xw = (const uint32_t*)Xs;
    const uint32_t* Ww = (const uint32_t*)Wt;

    float acc[3][2][4][4];
    #pragma unroll
    for (int w = 0; w < 3; w++)
        #pragma unroll
        for (int mf = 0; mf < 2; mf++)
            #pragma unroll
            for (int nf = 0; nf < 4; nf++)
                #pragma unroll
                for (int e = 0; e < 4; e++) acc[w][mf][nf][e] = 0.f;

    for (int kt = 0; kt < 16; kt++) {
        __syncthreads();
        #pragma unroll
        for (int it = 0; it < 8; it++) {
            int f = tid + it * 256, cc = f & 15, rr = f >> 4;
            float4 v = *(const float4*)&X[(size_t)(m0 + rr) * EMB + kt*64 + 4*cc];
            uint2 u;
            u.x = packh2(v.x, v.y);
            u.y = packh2(v.z, v.w);
            *(uint2*)&Xs[rr*72 + 4*cc] = u;
        }
        #pragma unroll
        for (int it = 0; it < 6; it++) {
            int f = tid + it * 256, w = f >> 9, rem = f & 511;
            int n = rem >> 3, cc = rem & 7;
            CP_ASYNC16(s32(&Wt[(w*64 + n)*72 + 8*cc]),
                       &g_Wth[(size_t)w * HEAD * EMB + (size_t)n * EMB + kt*64 + 8*cc]);
        }
        CP_COMMIT();
        CP_WAIT0();
        __syncthreads();

        #pragma unroll
        for (int j = 0; j < 4; j++) {
            uint32_t a[2][4];
            #pragma unroll
            for (int mf = 0; mf < 2; mf++) {
                const int m = mw*32 + mf*16;
                a[mf][0] = Xw[(m + r    )*36 + 8*j + c    ];
                a[mf][1] = Xw[(m + r + 8)*36 + 8*j + c    ];
                a[mf][2] = Xw[(m + r    )*36 + 8*j + c + 4];
                a[mf][3] = Xw[(m + r + 8)*36 + 8*j + c + 4];
            }
            #pragma unroll
            for (int w = 0; w < 3; w++) {
                uint32_t b[4][2];
                #pragma unroll
                for (int nf = 0; nf < 4; nf++) {
                    const int n = w*64 + nw*32 + nf*8;
                    b[nf][0] = Ww[(n + r)*36 + 8*j + c    ];
                    b[nf][1] = Ww[(n + r)*36 + 8*j + c + 4];
                }
                #pragma unroll
                for (int mf = 0; mf < 2; mf++)
                    #pragma unroll
                    for (int nf = 0; nf < 4; nf++)
                        mma_f16(acc[w][mf][nf], a[mf], b[nf]);
            }
        }
    }

    #pragma unroll
    for (int mf = 0; mf < 2; mf++) {
        const int mrow = m0 + mw*32 + mf*16 + r;
        #pragma unroll
        for (int nf = 0; nf < 4; nf++) {
            const int n = nw*32 + nf*8 + 2*c;
            *(uint32_t*)&g_Qh[(size_t)mrow * HEAD + n] =
                packh2(acc[0][mf][nf][0] * QSCALE, acc[0][mf][nf][1] * QSCALE);
            *(uint32_t*)&g_Qh[(size_t)(mrow + 8) * HEAD + n] =
                packh2(acc[0][mf][nf][2] * QSCALE, acc[0][mf][nf][3] * QSCALE);
            *(uint32_t*)&g_Kh[(size_t)mrow * HEAD + n] =
                packh2(acc[1][mf][nf][0], acc[1][mf][nf][1]);
            *(uint32_t*)&g_Kh[(size_t)(mrow + 8) * HEAD + n] =
                packh2(acc[1][mf][nf][2], acc[1][mf][nf][3]);
            g_Vth[(size_t)(n    ) * NTOK + mrow    ] = __float2half_rn(acc[2][mf][nf][0]);
            g_Vth[(size_t)(n + 1) * NTOK + mrow    ] = __float2half_rn(acc[2][mf][nf][1]);
            g_Vth[(size_t)(n    ) * NTOK + mrow + 8] = __float2half_rn(acc[2][mf][nf][2]);
            g_Vth[(size_t)(n + 1) * NTOK + mrow + 8] = __float2half_rn(acc[2][mf][nf][3]);
        }
    }
}

// ---------------------------------------------------------------------------
// Balanced bid -> (qb, batch) decode (validated R10/R14).
// ---------------------------------------------------------------------------
__device__ __forceinline__ void decode_bid(int bid, int& qb, int& b) {
    if (bid < 104)      { qb = bid >> 3;              b = bid & 7;   }
    else if (bid < 108) { qb = 13;                    b = bid - 104; }
    else if (bid < 148) {
        int i = bid - 108;
        if (i < 4)      { qb = 13;         b = 4 + i; }
        else if (i < 8) { qb = 18;         b = i;     }
        else            { int j = i - 8;   qb = 14 + (j >> 3); b = j & 7; }
    }
    else if (bid < 252) { int i = bid - 148; qb = 31 - (i >> 3); b = i & 7; }
    else                { qb = 18;                    b = bid - 252; }
}

// ---------------------------------------------------------------------------
// Kernel 2: flash attention, fp16 mma, warp-autonomous softmax, 2 CTAs/SM,
// DOUBLE-BUFFERED K/V (one barrier per tile; prefetch under compute).
// smem: Qs 9216 | Kb[2] 2x18432 | Vb[2] 2x17408 = 80896 B (2x = 162KB, fits)
// Combine buffer aliases Kb[0] (needs 18432 B exactly).
// ---------------------------------------------------------------------------
#define ATTN_SMEM_BYTES 80896

__global__ __launch_bounds__(256, 2) void attn_mma(float* __restrict__ out)
{
    extern __shared__ __align__(16) char smraw[];
    __half* Qs = (__half*)smraw;                                 // pitch 72h
    __half* KbA[2] = { (__half*)(smraw + 9216),
                       (__half*)(smraw + 9216 + 18432) };        // pitch 72h
    __half* VbA[2] = { (__half*)(smraw + 46080),
                       (__half*)(smraw + 46080 + 17408) };       // pitch 136h
    float*  Cb = (float*)(smraw + 9216);                         // alias Kb[0]

    const uint32_t* Qw = (const uint32_t*)Qs;

    const int tid  = threadIdx.x;
    const int wid  = tid >> 5;
    const int lane = tid & 31;
    const int mw   = wid >> 1;        // 0..3 (16 q-rows)
    const int nw   = wid & 1;         // 0..1 (private 64-key half)
    const int r    = lane >> 2;
    const int c    = lane & 3;

    int qb, b;
    decode_bid((int)blockIdx.x, qb, b);
    const int q0 = qb * 64;
    const int ntiles = q0 / 128 + 1;

    const __half* Qg = g_Qh + (size_t)b * SEQ * HEAD;
    const __half* Kg = g_Kh + (size_t)b * SEQ * HEAD;
    const __half* Vg = g_Vth + (size_t)b * SEQ;

    // prologue: stage Q + K(0),V(0) into buf 0
    #pragma unroll
    for (int it = 0; it < 2; it++) {
        int f = tid + it * 256, cc = f & 7, rr = f >> 3;
        CP_ASYNC16(s32(&Qs[rr*72 + 8*cc]),
                   &Qg[(size_t)(q0 + rr) * HEAD + 8*cc]);
    }
    #pragma unroll
    for (int it = 0; it < 4; it++) {
        int f = tid + it * 256;
        int kc = f & 7,  kr = f >> 3;
        CP_ASYNC16(s32(&KbA[0][kr*72 + 8*kc]), &Kg[(size_t)kr * HEAD + 8*kc]);
        int vc = f & 15, vr = f >> 4;
        CP_ASYNC16(s32(&VbA[0][vr*136 + 8*vc]), &Vg[(size_t)vr * NTOK + 8*vc]);
    }
    CP_COMMIT();

    float m_st[2] = { -1e29f, -1e29f };
    float l_st[2] = { 0.f, 0.f };
    float o[8][4];
    #pragma unroll
    for (int nf = 0; nf < 8; nf++)
        #pragma unroll
        for (int e = 0; e < 4; e++) o[nf][e] = 0.f;

    for (int kt = 0; kt < ntiles; kt++) {
        const int k0 = kt * 128;
        CP_WAIT0();
        __syncthreads();   // tile kt visible; all warps done with buf[(kt+1)&1]

        // prefetch tile kt+1 into the other buffer (flies under compute)
        if (kt + 1 < ntiles) {
            const int kn = (kt + 1) * 128;
            __half* Kn = KbA[(kt + 1) & 1];
            __half* Vn = VbA[(kt + 1) & 1];
            #pragma unroll
            for (int it = 0; it < 4; it++) {
                int f = tid + it * 256;
                int kc = f & 7,  kr = f >> 3;
                CP_ASYNC16(s32(&Kn[kr*72 + 8*kc]),
                           &Kg[(size_t)(kn + kr) * HEAD + 8*kc]);
                int vc = f & 15, vr = f >> 4;
                CP_ASYNC16(s32(&Vn[vr*136 + 8*vc]),
                           &Vg[(size_t)vr * NTOK + kn + 8*vc]);
            }
            CP_COMMIT();
        }

        const uint32_t* Kw = (const uint32_t*)KbA[kt & 1];
        const uint32_t* Vw = (const uint32_t*)VbA[kt & 1];

        // ----- S = Q K^T : warp tile 16q x 64keys, 4 k16 steps -----
        float s[8][4];
        #pragma unroll
        for (int nf = 0; nf < 8; nf++)
            #pragma unroll
            for (int e = 0; e < 4; e++) s[nf][e] = 0.f;

        #pragma unroll
        for (int j = 0; j < 4; j++) {
            uint32_t a[4];
            a[0] = Qw[(mw*16 + r    )*36 + 8*j + c    ];
            a[1] = Qw[(mw*16 + r + 8)*36 + 8*j + c    ];
            a[2] = Qw[(mw*16 + r    )*36 + 8*j + c + 4];
            a[3] = Qw[(mw*16 + r + 8)*36 + 8*j + c + 4];
            #pragma unroll
            for (int nf = 0; nf < 8; nf++) {
                const int n = nw*64 + nf*8;
                uint32_t bb[2];
                bb[0] = Kw[(n + r)*36 + 8*j + c    ];
                bb[1] = Kw[(n + r)*36 + 8*j + c + 4];
                mma_f16(s[nf], a, bb);
            }
        }

        // ----- causal mask -----
        const int row0 = q0 + mw*16 + r;
        const int row1 = row0 + 8;
        if (k0 + 127 > q0) {
            #pragma unroll
            for (int nf = 0; nf < 8; nf++) {
                const int col = k0 + nw*64 + nf*8 + 2*c;
                if (col     > row0) s[nf][0] = -1e30f;
                if (col + 1 > row0) s[nf][1] = -1e30f;
                if (col     > row1) s[nf][2] = -1e30f;
                if (col + 1 > row1) s[nf][3] = -1e30f;
            }
        }

        // ----- warp-local softmax -----
        float pm0 = s[0][0], pm1 = s[0][2];
        #pragma unroll
        for (int nf = 0; nf < 8; nf++) {
            pm0 = fmaxf(pm0, fmaxf(s[nf][0], s[nf][1]));
            pm1 = fmaxf(pm1, fmaxf(s[nf][2], s[nf][3]));
        }
        #pragma unroll
        for (int off = 1; off <= 2; off <<= 1) {
            pm0 = fmaxf(pm0, __shfl_xor_sync(0xffffffffu, pm0, off));
            pm1 = fmaxf(pm1, __shfl_xor_sync(0xffffffffu, pm1, off));
        }
        float mn0 = fmaxf(m_st[0], pm0);
        float mn1 = fmaxf(m_st[1], pm1);
        float corr0 = exp2f(m_st[0] - mn0);
        float corr1 = exp2f(m_st[1] - mn1);
        m_st[0] = mn0; m_st[1] = mn1;

        float rs0 = 0.f, rs1 = 0.f;
        #pragma unroll
        for (int nf = 0; nf < 8; nf++) {
            s[nf][0] = exp2f(s[nf][0] - mn0);
            s[nf][1] = exp2f(s[nf][1] - mn0);
            s[nf][2] = exp2f(s[nf][2] - mn1);
            s[nf][3] = exp2f(s[nf][3] - mn1);
            rs0 += s[nf][0] + s[nf][1];
            rs1 += s[nf][2] + s[nf][3];
        }
        #pragma unroll
        for (int off = 1; off <= 2; off <<= 1) {
            rs0 += __shfl_xor_sync(0xffffffffu, rs0, off);
            rs1 += __shfl_xor_sync(0xffffffffu, rs1, off);
        }
        l_st[0] = l_st[0] * corr0 + rs0;
        l_st[1] = l_st[1] * corr1 + rs1;

        #pragma unroll
        for (int nf = 0; nf < 8; nf++) {
            o[nf][0] *= corr0; o[nf][1] *= corr0;
            o[nf][2] *= corr1; o[nf][3] *= corr1;
        }

        // ----- O += P V : C-frag -> fp16 A-frag by pure packing -----
        #pragma unroll
        for (int j = 0; j < 4; j++) {
            uint32_t a[4];
            a[0] = packh2(s[2*j    ][0], s[2*j    ][1]);
            a[1] = packh2(s[2*j    ][2], s[2*j    ][3]);
            a[2] = packh2(s[2*j + 1][0], s[2*j + 1][1]);
            a[3] = packh2(s[2*j + 1][2], s[2*j + 1][3]);
            #pragma unroll
            for (int nf = 0; nf < 8; nf++) {
                const int n = nf*8;
                uint32_t bb[2];
                bb[0] = Vw[(n + r)*68 + nw*32 + 8*j + c    ];
                bb[1] = Vw[(n + r)*68 + nw*32 + 8*j + c + 4];
                mma_f16(o[nf], a, bb);
            }
        }
    }

    __syncthreads();   // all warps done with buffers -> Cb (=Kb[0]) free

    // ----- combine the two key-halves (split-KV merge) -----
    if (nw == 1) {
        float* dst = &Cb[(mw*32 + lane) * 36];
        #pragma unroll
        for (int nf = 0; nf < 8; nf++) {
            dst[nf*4 + 0] = o[nf][0]; dst[nf*4 + 1] = o[nf][1];
            dst[nf*4 + 2] = o[nf][2]; dst[nf*4 + 3] = o[nf][3];
        }
        dst[32] = m_st[0]; dst[33] = m_st[1];
        dst[34] = l_st[0]; dst[35] = l_st[1];
    }
    __syncthreads();
    if (nw == 0) {
        const float* src = &Cb[(mw*32 + lane) * 36];
        float pm0 = src[32], pm1 = src[33];
        float pl0 = src[34], pl1 = src[35];
        float M0 = fmaxf(m_st[0], pm0);
        float M1 = fmaxf(m_st[1], pm1);
        float c00 = exp2f(m_st[0] - M0), c01 = exp2f(pm0 - M0);
        float c10 = exp2f(m_st[1] - M1), c11 = exp2f(pm1 - M1);
        float L0 = l_st[0] * c00 + pl0 * c01;
        float L1 = l_st[1] * c10 + pl1 * c11;
        float inv0 = 1.f / L0, inv1 = 1.f / L1;

        const int row0 = q0 + mw*16 + r;
        #pragma unroll
        for (int nf = 0; nf < 8; nf++) {
            const int n = nf*8 + 2*c;
            float o0 = (o[nf][0] * c00 + src[nf*4 + 0] * c01) * inv0;
            float o1 = (o[nf][1] * c00 + src[nf*4 + 1] * c01) * inv0;
            float o2 = (o[nf][2] * c10 + src[nf*4 + 2] * c11) * inv1;
            float o3 = (o[nf][3] * c10 + src[nf*4 + 3] * c11) * inv1;
            *(float2*)&out[((size_t)b * SEQ + row0) * HEAD + n] =
                make_float2(o0, o1);
            *(float2*)&out[((size_t)b * SEQ + row0 + 8) * HEAD + n] =
                make_float2(o2, o3);
        }
    }
}

// ---------------------------------------------------------------------------
extern "C" void kernel_launch(void* const* d_in, const int* in_sizes, int n_in,
                              void* d_out, int out_size)
{
    const float* X  = (const float*)d_in[0];
    const float* Wq = (const float*)d_in[1];
    const float* Wk = (const float*)d_in[2];
    const float* Wv = (const float*)d_in[3];
    float* out = (float*)d_out;

    cudaFuncSetAttribute(attn_mma,
                         cudaFuncAttributeMaxDynamicSharedMemorySize, ATTN_SMEM_BYTES);

    dim3 g0(64, 3);
    wth_kernel<<<g0, 256>>>(Wq, Wk, Wv);

    qkv_mma<<<128, 256>>>(X);

    attn_mma<<<256, 256, ATTN_SMEM_BYTES>>>(out);
}

// round 17
// speedup vs baseline: 1.2020x; 1.2020x over previous
#include <cuda_runtime.h>
#include <cuda_fp16.h>
#include <cstdint>

#define BATCH 8
#define SEQ   2048
#define EMB   1024
#define HEAD  64
#define NTOK  (BATCH*SEQ)   // 16384
#define LOG2E 1.4426950408889634f
#define QSCALE (0.03125f * LOG2E)   // C^-0.5 * log2(e)

// ---------------------------------------------------------------------------
// PTX helpers (family-portable only)
// ---------------------------------------------------------------------------
__device__ __forceinline__ uint32_t packh2(float lo, float hi) {
    __half2 h = __floats2half2_rn(lo, hi);
    return *reinterpret_cast<uint32_t*>(&h);
}
__device__ __forceinline__ void mma_f16(float* d, const uint32_t* a, const uint32_t* b) {
    asm volatile(
        "mma.sync.aligned.m16n8k16.row.col.f32.f16.f16.f32 "
        "{%0,%1,%2,%3}, {%4,%5,%6,%7}, {%8,%9}, {%0,%1,%2,%3};"
        : "+f"(d[0]), "+f"(d[1]), "+f"(d[2]), "+f"(d[3])
        : "r"(a[0]), "r"(a[1]), "r"(a[2]), "r"(a[3]), "r"(b[0]), "r"(b[1]));
}
// ldmatrix x2 transposed b16: B-fragment loader from row-major [k][n] smem
__device__ __forceinline__ void ldsm_x2_t(uint32_t* d, uint32_t addr) {
    asm volatile("ldmatrix.sync.aligned.m8n8.x2.trans.shared.b16 {%0,%1}, [%2];"
        : "=r"(d[0]), "=r"(d[1]) : "r"(addr));
}
__device__ __forceinline__ uint32_t s32(const void* p) {
    return (uint32_t)__cvta_generic_to_shared(p);
}
#define CP_ASYNC16(dst, src) \
    asm volatile("cp.async.cg.shared.global [%0], [%1], 16;" :: "r"(dst), "l"(src))
#define CP_COMMIT() asm volatile("cp.async.commit_group;" ::: "memory")
#define CP_WAIT0()  asm volatile("cp.async.wait_group 0;" ::: "memory")

// ---------------------------------------------------------------------------
// device scratch: Q (pre-scaled), K, V all natural [tok][h] fp16
// ---------------------------------------------------------------------------
__device__ __half g_Qh[NTOK*HEAD];
__device__ __half g_Kh[NTOK*HEAD];
__device__ __half g_Vh[NTOK*HEAD];

// ---------------------------------------------------------------------------
// Kernel 1: QKV projection, mma.sync fp16.  W staged NATURAL [k][n] fp16;
// B-fragments via ldmatrix.x2.trans (no pre-transpose kernel needed).
// M-tile 128, K-tile 64, grid 128, 256 thr = 8 warps (4m x 2n).
// smem: Xs 128x72h (18432 B) | Ws 3x64x72h (27648 B) = 46080 B
// ---------------------------------------------------------------------------
__global__ __launch_bounds__(256, 1) void qkv_mma(
    const float* __restrict__ X,
    const float* __restrict__ Wq,
    const float* __restrict__ Wk,
    const float* __restrict__ Wv)
{
    __shared__ __half Xs[128*72];
    __shared__ __half Ws[3*64*72];   // [w*64 + k][n], pitch 72

    const int tid  = threadIdx.x;
    const int wid  = tid >> 5;
    const int lane = tid & 31;
    const int mw   = wid >> 1;
    const int nw   = wid & 1;
    const int m0   = blockIdx.x * 128;
    const int r = lane >> 2;
    const int c = lane & 3;
    const int l16 = lane & 15;

    const float* Wsrc[3] = { Wq, Wk, Wv };
    const uint32_t* Xw = (const uint32_t*)Xs;

    float acc[3][2][4][4];
    #pragma unroll
    for (int w = 0; w < 3; w++)
        #pragma unroll
        for (int mf = 0; mf < 2; mf++)
            #pragma unroll
            for (int nf = 0; nf < 4; nf++)
                #pragma unroll
                for (int e = 0; e < 4; e++) acc[w][mf][nf][e] = 0.f;

    for (int kt = 0; kt < 16; kt++) {
        __syncthreads();
        // X tile 128x64: fp32 f4 -> 2 half2 -> uint2 STS (8/thread)
        #pragma unroll
        for (int it = 0; it < 8; it++) {
            int f = tid + it * 256, cc = f & 15, rr = f >> 4;
            float4 v = *(const float4*)&X[(size_t)(m0 + rr) * EMB + kt*64 + 4*cc];
            uint2 u;
            u.x = packh2(v.x, v.y);
            u.y = packh2(v.z, v.w);
            *(uint2*)&Xs[rr*72 + 4*cc] = u;
        }
        // W tiles 3 x 64k x 64n natural: 3072 f4 (12/thread), packed fp16
        #pragma unroll
        for (int it = 0; it < 12; it++) {
            int f = tid + it * 256, w = f >> 10, rem = f & 1023;
            int k = rem >> 4, nc = rem & 15;
            float4 v = *(const float4*)&Wsrc[w][(size_t)(kt*64 + k) * HEAD + 4*nc];
            uint2 u;
            u.x = packh2(v.x, v.y);
            u.y = packh2(v.z, v.w);
            *(uint2*)&Ws[(w*64 + k)*72 + 4*nc] = u;
        }
        __syncthreads();

        #pragma unroll
        for (int j = 0; j < 4; j++) {          // 4 k16 steps
            uint32_t a[2][4];
            #pragma unroll
            for (int mf = 0; mf < 2; mf++) {
                const int m = mw*32 + mf*16;
                a[mf][0] = Xw[(m + r    )*36 + 8*j + c    ];
                a[mf][1] = Xw[(m + r + 8)*36 + 8*j + c    ];
                a[mf][2] = Xw[(m + r    )*36 + 8*j + c + 4];
                a[mf][3] = Xw[(m + r + 8)*36 + 8*j + c + 4];
            }
            #pragma unroll
            for (int w = 0; w < 3; w++) {
                #pragma unroll
                for (int nf = 0; nf < 4; nf++) {
                    const int n0 = nw*32 + nf*8;
                    uint32_t bb[2];
                    ldsm_x2_t(bb, s32(&Ws[(w*64 + 16*j + l16)*72 + n0]));
                    #pragma unroll
                    for (int mf = 0; mf < 2; mf++)
                        mma_f16(acc[w][mf][nf], a[mf], bb);
                }
            }
        }
    }

    // epilogue: Q pre-scaled; Q,K,V all coalesced natural fp16 stores
    #pragma unroll
    for (int mf = 0; mf < 2; mf++) {
        const int mrow = m0 + mw*32 + mf*16 + r;
        #pragma unroll
        for (int nf = 0; nf < 4; nf++) {
            const int n = nw*32 + nf*8 + 2*c;
            *(uint32_t*)&g_Qh[(size_t)mrow * HEAD + n] =
                packh2(acc[0][mf][nf][0] * QSCALE, acc[0][mf][nf][1] * QSCALE);
            *(uint32_t*)&g_Qh[(size_t)(mrow + 8) * HEAD + n] =
                packh2(acc[0][mf][nf][2] * QSCALE, acc[0][mf][nf][3] * QSCALE);
            *(uint32_t*)&g_Kh[(size_t)mrow * HEAD + n] =
                packh2(acc[1][mf][nf][0], acc[1][mf][nf][1]);
            *(uint32_t*)&g_Kh[(size_t)(mrow + 8) * HEAD + n] =
                packh2(acc[1][mf][nf][2], acc[1][mf][nf][3]);
            *(uint32_t*)&g_Vh[(size_t)mrow * HEAD + n] =
                packh2(acc[2][mf][nf][0], acc[2][mf][nf][1]);
            *(uint32_t*)&g_Vh[(size_t)(mrow + 8) * HEAD + n] =
                packh2(acc[2][mf][nf][2], acc[2][mf][nf][3]);
        }
    }
}

// ---------------------------------------------------------------------------
// Balanced bid -> (qb, batch) decode (validated R10/R14).
// ---------------------------------------------------------------------------
__device__ __forceinline__ void decode_bid(int bid, int& qb, int& b) {
    if (bid < 104)      { qb = bid >> 3;              b = bid & 7;   }
    else if (bid < 108) { qb = 13;                    b = bid - 104; }
    else if (bid < 148) {
        int i = bid - 108;
        if (i < 4)      { qb = 13;         b = 4 + i; }
        else if (i < 8) { qb = 18;         b = i;     }
        else            { int j = i - 8;   qb = 14 + (j >> 3); b = j & 7; }
    }
    else if (bid < 252) { int i = bid - 148; qb = 31 - (i >> 3); b = i & 7; }
    else                { qb = 18;                    b = bid - 252; }
}

// ---------------------------------------------------------------------------
// Kernel 2: flash attention, fp16 mma, warp-autonomous softmax, 2 CTAs/SM.
// R15's proven single-buffered shape; V staged NATURAL [key][h] and PV
// B-frags loaded via ldmatrix.x2.trans (HW transpose).
// smem: Qs 9216 | Ks 128x72h 18432 (aliased by combine buf) | Vs 18432
// = 46080 B  (2 CTAs/SM = 92 KB)
// ---------------------------------------------------------------------------
#define ATTN_SMEM_BYTES 46080

__global__ __launch_bounds__(256, 2) void attn_mma(float* __restrict__ out)
{
    extern __shared__ __align__(16) char smraw[];
    __half* Qs = (__half*)smraw;               // pitch 72h
    __half* Ks = (__half*)(smraw + 9216);      // pitch 72h, 128 rows
    __half* Vs = (__half*)(smraw + 27648);     // pitch 72h, 128 rows (natural)
    float*  Cb = (float*)(smraw + 9216);       // combine buf (aliases Ks)

    const uint32_t* Qw = (const uint32_t*)Qs;
    const uint32_t* Kw = (const uint32_t*)Ks;

    const int tid  = threadIdx.x;
    const int wid  = tid >> 5;
    const int lane = tid & 31;
    const int mw   = wid >> 1;        // 0..3 (16 q-rows)
    const int nw   = wid & 1;         // 0..1 (private 64-key half)
    const int r    = lane >> 2;
    const int c    = lane & 3;
    const int l16  = lane & 15;

    int qb, b;
    decode_bid((int)blockIdx.x, qb, b);
    const int q0 = qb * 64;
    const int ntiles = q0 / 128 + 1;

    const __half* Qg = g_Qh + (size_t)b * SEQ * HEAD;
    const __half* Kg = g_Kh + (size_t)b * SEQ * HEAD;
    const __half* Vg = g_Vh + (size_t)b * SEQ * HEAD;

    // prologue: stage Q
    #pragma unroll
    for (int it = 0; it < 2; it++) {
        int f = tid + it * 256, cc = f & 7, rr = f >> 3;
        CP_ASYNC16(s32(&Qs[rr*72 + 8*cc]),
                   &Qg[(size_t)(q0 + rr) * HEAD + 8*cc]);
    }
    CP_COMMIT();

    float m_st[2] = { -1e29f, -1e29f };
    float l_st[2] = { 0.f, 0.f };
    float o[8][4];
    #pragma unroll
    for (int nf = 0; nf < 8; nf++)
        #pragma unroll
        for (int e = 0; e < 4; e++) o[nf][e] = 0.f;

    for (int kt = 0; kt < ntiles; kt++) {
        const int k0 = kt * 128;
        __syncthreads();   // all warps done with tile kt-1 smem

        // stage K,V natural (1024 chunks each, 4+4 per thread)
        #pragma unroll
        for (int it = 0; it < 4; it++) {
            int f = tid + it * 256, kc = f & 7, kr = f >> 3;
            CP_ASYNC16(s32(&Ks[kr*72 + 8*kc]),
                       &Kg[(size_t)(k0 + kr) * HEAD + 8*kc]);
            CP_ASYNC16(s32(&Vs[kr*72 + 8*kc]),
                       &Vg[(size_t)(k0 + kr) * HEAD + 8*kc]);
        }
        CP_COMMIT();
        CP_WAIT0();
        __syncthreads();   // tile kt (and Q on kt=0) visible

        // ----- S = Q K^T : warp tile 16q x 64keys, 4 k16 steps -----
        float s[8][4];
        #pragma unroll
        for (int nf = 0; nf < 8; nf++)
            #pragma unroll
            for (int e = 0; e < 4; e++) s[nf][e] = 0.f;

        #pragma unroll
        for (int j = 0; j < 4; j++) {
            uint32_t a[4];
            a[0] = Qw[(mw*16 + r    )*36 + 8*j + c    ];
            a[1] = Qw[(mw*16 + r + 8)*36 + 8*j + c    ];
            a[2] = Qw[(mw*16 + r    )*36 + 8*j + c + 4];
            a[3] = Qw[(mw*16 + r + 8)*36 + 8*j + c + 4];
            #pragma unroll
            for (int nf = 0; nf < 8; nf++) {
                const int n = nw*64 + nf*8;
                uint32_t bb[2];
                bb[0] = Kw[(n + r)*36 + 8*j + c    ];
                bb[1] = Kw[(n + r)*36 + 8*j + c + 4];
                mma_f16(s[nf], a, bb);
            }
        }

        // ----- causal mask -----
        const int row0 = q0 + mw*16 + r;
        const int row1 = row0 + 8;
        if (k0 + 127 > q0) {
            #pragma unroll
            for (int nf = 0; nf < 8; nf++) {
                const int col = k0 + nw*64 + nf*8 + 2*c;
                if (col     > row0) s[nf][0] = -1e30f;
                if (col + 1 > row0) s[nf][1] = -1e30f;
                if (col     > row1) s[nf][2] = -1e30f;
                if (col + 1 > row1) s[nf][3] = -1e30f;
            }
        }

        // ----- warp-local softmax -----
        float pm0 = s[0][0], pm1 = s[0][2];
        #pragma unroll
        for (int nf = 0; nf < 8; nf++) {
            pm0 = fmaxf(pm0, fmaxf(s[nf][0], s[nf][1]));
            pm1 = fmaxf(pm1, fmaxf(s[nf][2], s[nf][3]));
        }
        #pragma unroll
        for (int off = 1; off <= 2; off <<= 1) {
            pm0 = fmaxf(pm0, __shfl_xor_sync(0xffffffffu, pm0, off));
            pm1 = fmaxf(pm1, __shfl_xor_sync(0xffffffffu, pm1, off));
        }
        float mn0 = fmaxf(m_st[0], pm0);
        float mn1 = fmaxf(m_st[1], pm1);
        float corr0 = exp2f(m_st[0] - mn0);
        float corr1 = exp2f(m_st[1] - mn1);
        m_st[0] = mn0; m_st[1] = mn1;

        float rs0 = 0.f, rs1 = 0.f;
        #pragma unroll
        for (int nf = 0; nf < 8; nf++) {
            s[nf][0] = exp2f(s[nf][0] - mn0);
            s[nf][1] = exp2f(s[nf][1] - mn0);
            s[nf][2] = exp2f(s[nf][2] - mn1);
            s[nf][3] = exp2f(s[nf][3] - mn1);
            rs0 += s[nf][0] + s[nf][1];
            rs1 += s[nf][2] + s[nf][3];
        }
        #pragma unroll
        for (int off = 1; off <= 2; off <<= 1) {
            rs0 += __shfl_xor_sync(0xffffffffu, rs0, off);
            rs1 += __shfl_xor_sync(0xffffffffu, rs1, off);
        }
        l_st[0] = l_st[0] * corr0 + rs0;
        l_st[1] = l_st[1] * corr1 + rs1;

        #pragma unroll
        for (int nf = 0; nf < 8; nf++) {
            o[nf][0] *= corr0; o[nf][1] *= corr0;
            o[nf][2] *= corr1; o[nf][3] *= corr1;
        }

        // ----- O += P V : A = packed C-frags; B via ldmatrix.x2.trans -----
        #pragma unroll
        for (int j = 0; j < 4; j++) {
            uint32_t a[4];
            a[0] = packh2(s[2*j    ][0], s[2*j    ][1]);
            a[1] = packh2(s[2*j    ][2], s[2*j    ][3]);
            a[2] = packh2(s[2*j + 1][0], s[2*j + 1][1]);
            a[3] = packh2(s[2*j + 1][2], s[2*j + 1][3]);
            const int krow = nw*64 + 16*j + l16;
            #pragma unroll
            for (int nf = 0; nf < 8; nf++) {
                uint32_t bb[2];
                ldsm_x2_t(bb, s32(&Vs[krow*72 + nf*8]));
                mma_f16(o[nf], a, bb);
            }
        }
    }

    __syncthreads();   // all warps done with Ks/Vs -> Cb (=Ks) free

    // ----- combine the two key-halves (split-KV merge) -----
    if (nw == 1) {
        float* dst = &Cb[(mw*32 + lane) * 36];
        #pragma unroll
        for (int nf = 0; nf < 8; nf++) {
            dst[nf*4 + 0] = o[nf][0]; dst[nf*4 + 1] = o[nf][1];
            dst[nf*4 + 2] = o[nf][2]; dst[nf*4 + 3] = o[nf][3];
        }
        dst[32] = m_st[0]; dst[33] = m_st[1];
        dst[34] = l_st[0]; dst[35] = l_st[1];
    }
    __syncthreads();
    if (nw == 0) {
        const float* src = &Cb[(mw*32 + lane) * 36];
        float pm0 = src[32], pm1 = src[33];
        float pl0 = src[34], pl1 = src[35];
        float M0 = fmaxf(m_st[0], pm0);
        float M1 = fmaxf(m_st[1], pm1);
        float c00 = exp2f(m_st[0] - M0), c01 = exp2f(pm0 - M0);
        float c10 = exp2f(m_st[1] - M1), c11 = exp2f(pm1 - M1);
        float L0 = l_st[0] * c00 + pl0 * c01;
        float L1 = l_st[1] * c10 + pl1 * c11;
        float inv0 = 1.f / L0, inv1 = 1.f / L1;

        const int row0 = q0 + mw*16 + r;
        #pragma unroll
        for (int nf = 0; nf < 8; nf++) {
            const int n = nf*8 + 2*c;
            float o0 = (o[nf][0] * c00 + src[nf*4 + 0] * c01) * inv0;
            float o1 = (o[nf][1] * c00 + src[nf*4 + 1] * c01) * inv0;
            float o2 = (o[nf][2] * c10 + src[nf*4 + 2] * c11) * inv1;
            float o3 = (o[nf][3] * c10 + src[nf*4 + 3] * c11) * inv1;
            *(float2*)&out[((size_t)b * SEQ + row0) * HEAD + n] =
                make_float2(o0, o1);
            *(float2*)&out[((size_t)b * SEQ + row0 + 8) * HEAD + n] =
                make_float2(o2, o3);
        }
    }
}

// ---------------------------------------------------------------------------
extern "C" void kernel_launch(void* const* d_in, const int* in_sizes, int n_in,
                              void* d_out, int out_size)
{
    const float* X  = (const float*)d_in[0];
    const float* Wq = (const float*)d_in[1];
    const float* Wk = (const float*)d_in[2];
    const float* Wv = (const float*)d_in[3];
    float* out = (float*)d_out;

    cudaFuncSetAttribute(attn_mma,
                         cudaFuncAttributeMaxDynamicSharedMemorySize, ATTN_SMEM_BYTES);

    qkv_mma<<<128, 256>>>(X, Wq, Wk, Wv);

    attn_mma<<<256, 256, ATTN_SMEM_BYTES>>>(out);
}